// round 2
// baseline (speedup 1.0000x reference)
#include <cuda_runtime.h>

// Problem constants (fixed shapes per reference)
#define M_OUT   125000
#define KNB     8
#define CIN     96
#define COUT    192
#define KTOT    (KNB * CIN)          // 768
#define BM      64
#define BK      32
#define NCHUNK  (KTOT / BK)          // 24
#define NBLK    ((M_OUT + BM - 1) / BM)   // 1954
#define BN_EPS  1e-5f

// Deterministic scratch (no allocs allowed) — partials laid out [channel][block]
// so the stats reduction is coalesced over blocks.
__device__ float g_psum[COUT * NBLK];
__device__ float g_psq[COUT * NBLK];
__device__ float g_scale[COUT];
__device__ float g_shift[COUT];
__device__ int   g_is64;             // 1 if neigh buffer is int64, 0 if int32

// ---------------------------------------------------------------------------
// Detect neigh dtype: reinterpret as int32 pairs. For an int64 buffer of
// non-negative indices < 2^31, every odd int32 word is 0. For an int32 buffer
// of 1M random indices, some of the first 8192 words are certainly nonzero.
// ---------------------------------------------------------------------------
__global__ void detect_kernel(const int* __restrict__ neigh32)
{
    if (threadIdx.x == 0 && blockIdx.x == 0) {
        int is64 = 1;
        for (int i = 0; i < 4096; ++i) {
            if (neigh32[2 * i + 1] != 0) { is64 = 0; break; }
        }
        g_is64 = is64;
    }
}

// ---------------------------------------------------------------------------
// Conv kernel: implicit-gather GEMM. Block = 64 rows x 192 cols, 16x16 threads,
// each thread owns a 4x12 register tile (rows strided 16, cols strided 16).
// ---------------------------------------------------------------------------
__global__ __launch_bounds__(256) void conv_kernel(
    const float* __restrict__ data,
    const float* __restrict__ weights,
    const float* __restrict__ bias,
    const void* __restrict__ neigh_raw,
    float* __restrict__ out)
{
    __shared__ float As[BM][BK + 1];       // +1 pad: conflict-free column reads
    __shared__ float Bs[BK][COUT];
    __shared__ int   Srow[BM][KNB];        // gather source row per (tile-row, kk); -1 = empty
    __shared__ float Red[16][COUT];        // cross-ty reduction buffer for BN partials

    const int tx  = threadIdx.x;           // 0..15 -> column group
    const int ty  = threadIdx.y;           // 0..15 -> row group
    const int tid = ty * 16 + tx;
    const int bx  = blockIdx.x;
    const int m0  = bx * BM;

    const int is64 = g_is64;
    const long long* neigh64 = (const long long*)neigh_raw;
    const int*       neigh32 = (const int*)neigh_raw;

    // Stage neighbor indices for this row tile.
    for (int idx = tid; idx < BM * KNB; idx += 256) {
        int r  = idx >> 3;
        int kk = idx & 7;
        int m  = m0 + r;
        int srow = -1;
        if (m < M_OUT) {
            long long v;
            if (is64) v = neigh64[(long long)m * KNB + kk];
            else      v = (long long)neigh32[(long long)m * KNB + kk];
            if (v >= 0 && v < (long long)1000000000) srow = (int)v;
        }
        Srow[r][kk] = srow;
    }
    __syncthreads();

    float acc[4][12];
#pragma unroll
    for (int i = 0; i < 4; ++i)
#pragma unroll
        for (int j = 0; j < 12; ++j) acc[i][j] = 0.0f;

    // K loop: 24 chunks of 32. Each chunk lies inside a single kk (96 = 3*32).
    for (int t = 0; t < NCHUNK; ++t) {
        const int kk = t / 3;
        const int c0 = (t % 3) * BK;

        // Load A tile (gathered, coalesced per 32-float row segment)
        for (int idx = tid; idx < BM * BK; idx += 256) {
            int r = idx >> 5;
            int c = idx & 31;
            int srow = Srow[r][kk];
            As[r][c] = (srow >= 0) ? data[(long long)srow * CIN + c0 + c] : 0.0f;
        }
        // Load B tile (weights), fully coalesced
        for (int idx = tid; idx < BK * COUT; idx += 256) {
            int kc = idx / COUT;
            int c  = idx - kc * COUT;
            Bs[kc][c] = weights[(long long)(kk * CIN + c0 + kc) * COUT + c];
        }
        __syncthreads();

#pragma unroll 8
        for (int kc = 0; kc < BK; ++kc) {
            float a[4];
#pragma unroll
            for (int i = 0; i < 4; ++i) a[i] = As[ty + 16 * i][kc];
            float b[12];
#pragma unroll
            for (int j = 0; j < 12; ++j) b[j] = Bs[kc][tx + 16 * j];
#pragma unroll
            for (int i = 0; i < 4; ++i)
#pragma unroll
                for (int j = 0; j < 12; ++j) acc[i][j] = fmaf(a[i], b[j], acc[i][j]);
        }
        __syncthreads();
    }

    // Epilogue: add bias, write output, accumulate per-channel BN partials
    float bj[12];
#pragma unroll
    for (int j = 0; j < 12; ++j) bj[j] = __ldg(&bias[tx + 16 * j]);

    float colsum[12], colsq[12];
#pragma unroll
    for (int j = 0; j < 12; ++j) { colsum[j] = 0.0f; colsq[j] = 0.0f; }

#pragma unroll
    for (int i = 0; i < 4; ++i) {
        int m = m0 + ty + 16 * i;
        bool valid = (m < M_OUT);
#pragma unroll
        for (int j = 0; j < 12; ++j) {
            float v = acc[i][j] + bj[j];
            if (valid) {
                out[(long long)m * COUT + tx + 16 * j] = v;
                colsum[j] += v;
                colsq[j]  += v * v;
            }
        }
    }

    // Deterministic cross-ty reduction (16 partials per channel)
#pragma unroll
    for (int j = 0; j < 12; ++j) Red[ty][tx + 16 * j] = colsum[j];
    __syncthreads();
    if (tid < COUT) {
        float s = 0.0f;
#pragma unroll
        for (int y = 0; y < 16; ++y) s += Red[y][tid];
        g_psum[tid * NBLK + bx] = s;
    }
    __syncthreads();
#pragma unroll
    for (int j = 0; j < 12; ++j) Red[ty][tx + 16 * j] = colsq[j];
    __syncthreads();
    if (tid < COUT) {
        float s = 0.0f;
#pragma unroll
        for (int y = 0; y < 16; ++y) s += Red[y][tid];
        g_psq[tid * NBLK + bx] = s;
    }
}

// ---------------------------------------------------------------------------
// Stats kernel: one block per channel, reduce 1954 partials, emit fused
// scale/shift:  y = x*scale + shift,  scale = gamma*rsqrt(var+eps),
// shift = beta - mean*scale.
// ---------------------------------------------------------------------------
__global__ __launch_bounds__(256) void stats_kernel(
    const float* __restrict__ gamma,
    const float* __restrict__ beta)
{
    const int c = blockIdx.x;
    const int t = threadIdx.x;
    float s = 0.0f, q = 0.0f;
    for (int b = t; b < NBLK; b += 256) {
        s += g_psum[c * NBLK + b];
        q += g_psq[c * NBLK + b];
    }
    __shared__ float ss[256], sq[256];
    ss[t] = s; sq[t] = q;
    __syncthreads();
    for (int o = 128; o > 0; o >>= 1) {
        if (t < o) { ss[t] += ss[t + o]; sq[t] += sq[t + o]; }
        __syncthreads();
    }
    if (t == 0) {
        float mean = ss[0] / (float)M_OUT;
        float var  = sq[0] / (float)M_OUT - mean * mean;
        float rs   = rsqrtf(var + BN_EPS);
        float sc   = gamma[c] * rs;
        g_scale[c] = sc;
        g_shift[c] = beta[c] - mean * sc;
    }
}

// ---------------------------------------------------------------------------
// Normalize kernel: in-place float4 affine over d_out.
// ---------------------------------------------------------------------------
#define NVEC (M_OUT * COUT / 4)   // 6,000,000
__global__ __launch_bounds__(256) void norm_kernel(float4* __restrict__ out4)
{
    int i = blockIdx.x * 256 + threadIdx.x;
    if (i < NVEC) {
        int c = (i % 48) * 4;      // (i*4) % 192, float4 never crosses channel wrap
        float4 v = out4[i];
        v.x = v.x * g_scale[c + 0] + g_shift[c + 0];
        v.y = v.y * g_scale[c + 1] + g_shift[c + 1];
        v.z = v.z * g_scale[c + 2] + g_shift[c + 2];
        v.w = v.w * g_scale[c + 3] + g_shift[c + 3];
        out4[i] = v;
    }
}

extern "C" void kernel_launch(void* const* d_in, const int* in_sizes, int n_in,
                              void* d_out, int out_size)
{
    const float* data    = (const float*)d_in[0];
    const float* weights = (const float*)d_in[1];
    const float* bias    = (const float*)d_in[2];
    const float* gamma   = (const float*)d_in[3];
    const float* beta    = (const float*)d_in[4];
    const void*  neigh   = (const void*)d_in[5];
    float* out = (float*)d_out;

    detect_kernel<<<1, 32>>>((const int*)neigh);
    dim3 cblk(16, 16);
    conv_kernel<<<NBLK, cblk>>>(data, weights, bias, neigh, out);
    stats_kernel<<<COUT, 256>>>(gamma, beta);
    norm_kernel<<<(NVEC + 255) / 256, 256>>>((float4*)out);
}

// round 3
// speedup vs baseline: 2.1796x; 2.1796x over previous
#include <cuda_runtime.h>
#include <cuda_bf16.h>

// Problem constants (fixed shapes per reference)
#define M_OUT   125000
#define KNB     8
#define CIN     96
#define COUT    192
#define KTOT    (KNB * CIN)               // 768
#define BM      64
#define BK      32
#define NCHUNK  (KTOT / BK)               // 24
#define NBLK    ((M_OUT + BM - 1) / BM)   // 1954
#define BN_EPS  1e-5f
#define SSTR    20                        // smem row stride in 32-bit words (bank-conflict-free)

// Deterministic scratch (no allocs allowed)
__device__ float g_psum[COUT * NBLK];
__device__ float g_psq[COUT * NBLK];
__device__ float g_scale[COUT];
__device__ float g_shift[COUT];
__device__ int   g_is64;
// Pre-split weights: [chunk t][n][w] packed bf16x2 over k-pairs (k = t*32 + 2w, 2w+1)
__device__ unsigned g_wh[NCHUNK * COUT * 16];
__device__ unsigned g_wl[NCHUNK * COUT * 16];

// ---------------------------------------------------------------------------
// Detect neigh dtype (int64 vs silently-downcast int32).
// ---------------------------------------------------------------------------
__global__ void detect_kernel(const int* __restrict__ neigh32)
{
    if (threadIdx.x == 0 && blockIdx.x == 0) {
        int is64 = 1;
        for (int i = 0; i < 4096; ++i) {
            if (neigh32[2 * i + 1] != 0) { is64 = 0; break; }
        }
        g_is64 = is64;
    }
}

// ---------------------------------------------------------------------------
// Prepack weights: fp32 [768][192] -> hi/lo bf16x2 in [t][n][k/2] layout.
// ---------------------------------------------------------------------------
__global__ __launch_bounds__(256) void prepack_kernel(const float* __restrict__ W)
{
    const int t = blockIdx.x;
    for (int idx = threadIdx.x; idx < COUT * 16; idx += 256) {
        int n = idx % COUT;
        int w = idx / COUT;
        float f0 = W[(long long)(t * 32 + 2 * w) * COUT + n];
        float f1 = W[(long long)(t * 32 + 2 * w + 1) * COUT + n];
        __nv_bfloat162 h = __floats2bfloat162_rn(f0, f1);   // .x = f0 (low 16b)
        float2 hf = __bfloat1622float2(h);
        __nv_bfloat162 l = __floats2bfloat162_rn(f0 - hf.x, f1 - hf.y);
        g_wh[(t * COUT + n) * 16 + w] = *reinterpret_cast<unsigned*>(&h);
        g_wl[(t * COUT + n) * 16 + w] = *reinterpret_cast<unsigned*>(&l);
    }
}

// ---------------------------------------------------------------------------
// Conv kernel: implicit-gather GEMM on tensor cores (bf16 hi/lo split, 3 MMAs).
// Block = 64 rows x 192 cols, 8 warps as 4(M) x 2(N); warp tile 16x96.
// ---------------------------------------------------------------------------
#define MMA16816(d, a0, a1, a2, a3, b0, b1)                                   \
    asm volatile(                                                             \
        "mma.sync.aligned.m16n8k16.row.col.f32.bf16.bf16.f32 "                \
        "{%0,%1,%2,%3}, {%4,%5,%6,%7}, {%8,%9}, {%0,%1,%2,%3};"               \
        : "+f"(d[0]), "+f"(d[1]), "+f"(d[2]), "+f"(d[3])                      \
        : "r"(a0), "r"(a1), "r"(a2), "r"(a3), "r"(b0), "r"(b1))

__global__ __launch_bounds__(256) void conv_kernel(
    const float* __restrict__ data,
    const float* __restrict__ bias,
    const void* __restrict__ neigh_raw,
    float* __restrict__ out)
{
    // smem pool: Ah(64*SSTR) Al(64*SSTR) Bh(192*SSTR) Bl(192*SSTR) Srow(64*8)
    // Red (2*4*192 floats) overlays the A buffers after the MMA loop.
    __shared__ unsigned pool[64 * SSTR * 2 + COUT * SSTR * 2 + BM * KNB];
    unsigned* Ah = pool;
    unsigned* Al = Ah + 64 * SSTR;
    unsigned* Bh = Al + 64 * SSTR;
    unsigned* Bl = Bh + COUT * SSTR;
    int*   Srow  = (int*)(Bl + COUT * SSTR);
    float* RedS  = (float*)pool;                 // [4][192]
    float* RedQ  = RedS + 4 * COUT;              // [4][192]

    const int tid = threadIdx.x;
    const int lid = tid & 31;
    const int wid = tid >> 5;            // 0..7
    const int wm  = wid >> 1;            // 0..3 (M)
    const int wn  = wid & 1;             // 0..1 (N)
    const int gid = lid >> 2;            // 0..7
    const int tig = lid & 3;             // 0..3
    const int bx  = blockIdx.x;
    const int m0  = bx * BM;

    const int is64 = g_is64;
    const long long* neigh64 = (const long long*)neigh_raw;
    const int*       neigh32 = (const int*)neigh_raw;

    // Stage neighbor indices for this row tile.
    for (int idx = tid; idx < BM * KNB; idx += 256) {
        int r  = idx >> 3;
        int kk = idx & 7;
        int m  = m0 + r;
        int srow = -1;
        if (m < M_OUT) {
            long long v = is64 ? neigh64[(long long)m * KNB + kk]
                               : (long long)neigh32[(long long)m * KNB + kk];
            if (v >= 0 && v < (long long)1000000000) srow = (int)v;
        }
        Srow[r * KNB + kk] = srow;
    }

    float acc[12][4];
#pragma unroll
    for (int j = 0; j < 12; ++j)
#pragma unroll
        for (int q = 0; q < 4; ++q) acc[j][q] = 0.0f;

    const int rowA0 = wm * 16 + gid;
    const int rowA1 = rowA0 + 8;

    for (int t = 0; t < NCHUNK; ++t) {
        const int kk = t / 3;
        const int c0 = (t % 3) * BK;
        __syncthreads();   // protect smem from previous iteration's readers

        // A: gather fp32, split to hi/lo bf16x2, store to smem
        for (int idx = tid; idx < BM * 16; idx += 256) {
            int r = idx >> 4;
            int w = idx & 15;
            int srow = Srow[r * KNB + kk];
            float2 f = make_float2(0.0f, 0.0f);
            if (srow >= 0) f = *(const float2*)&data[(long long)srow * CIN + c0 + 2 * w];
            __nv_bfloat162 h = __floats2bfloat162_rn(f.x, f.y);
            float2 hf = __bfloat1622float2(h);
            __nv_bfloat162 l = __floats2bfloat162_rn(f.x - hf.x, f.y - hf.y);
            Ah[r * SSTR + w] = *reinterpret_cast<unsigned*>(&h);
            Al[r * SSTR + w] = *reinterpret_cast<unsigned*>(&l);
        }
        // B: straight copy of pre-split packed weights
        for (int idx = tid; idx < COUT * 16; idx += 256) {
            int n = idx >> 4;
            int w = idx & 15;
            Bh[n * SSTR + w] = g_wh[(t * COUT + n) * 16 + w];
            Bl[n * SSTR + w] = g_wl[(t * COUT + n) * 16 + w];
        }
        __syncthreads();

        // A fragments for both k16 steps
        unsigned ah[2][4], al[2][4];
#pragma unroll
        for (int s = 0; s < 2; ++s) {
            ah[s][0] = Ah[rowA0 * SSTR + s * 8 + tig];
            ah[s][1] = Ah[rowA1 * SSTR + s * 8 + tig];
            ah[s][2] = Ah[rowA0 * SSTR + s * 8 + 4 + tig];
            ah[s][3] = Ah[rowA1 * SSTR + s * 8 + 4 + tig];
            al[s][0] = Al[rowA0 * SSTR + s * 8 + tig];
            al[s][1] = Al[rowA1 * SSTR + s * 8 + tig];
            al[s][2] = Al[rowA0 * SSTR + s * 8 + 4 + tig];
            al[s][3] = Al[rowA1 * SSTR + s * 8 + 4 + tig];
        }

#pragma unroll
        for (int j = 0; j < 12; ++j) {
            const int n = wn * 96 + j * 8 + gid;
            unsigned bh0 = Bh[n * SSTR + tig],     bh1 = Bh[n * SSTR + 4 + tig];
            unsigned bh2 = Bh[n * SSTR + 8 + tig], bh3 = Bh[n * SSTR + 12 + tig];
            unsigned bl0 = Bl[n * SSTR + tig],     bl1 = Bl[n * SSTR + 4 + tig];
            unsigned bl2 = Bl[n * SSTR + 8 + tig], bl3 = Bl[n * SSTR + 12 + tig];
            // kstep 0
            MMA16816(acc[j], ah[0][0], ah[0][1], ah[0][2], ah[0][3], bh0, bh1);
            MMA16816(acc[j], ah[0][0], ah[0][1], ah[0][2], ah[0][3], bl0, bl1);
            MMA16816(acc[j], al[0][0], al[0][1], al[0][2], al[0][3], bh0, bh1);
            // kstep 1
            MMA16816(acc[j], ah[1][0], ah[1][1], ah[1][2], ah[1][3], bh2, bh3);
            MMA16816(acc[j], ah[1][0], ah[1][1], ah[1][2], ah[1][3], bl2, bl3);
            MMA16816(acc[j], al[1][0], al[1][1], al[1][2], al[1][3], bh2, bh3);
        }
    }
    __syncthreads();   // all MMA smem reads done; Red may overlay A

    // Epilogue: bias + output store + per-lane column sums for BN
    const int r0 = m0 + rowA0;
    const int r1 = m0 + rowA1;
    const bool v0 = (r0 < M_OUT);
    const bool v1 = (r1 < M_OUT);

    float cs[24], cq[24];
#pragma unroll
    for (int j = 0; j < 12; ++j) {
        const int cb = wn * 96 + j * 8 + 2 * tig;
        float b0 = __ldg(&bias[cb]);
        float b1 = __ldg(&bias[cb + 1]);
        float v00 = acc[j][0] + b0, v01 = acc[j][1] + b1;   // row r0
        float v10 = acc[j][2] + b0, v11 = acc[j][3] + b1;   // row r1
        if (v0) *(float2*)&out[(long long)r0 * COUT + cb] = make_float2(v00, v01);
        if (v1) *(float2*)&out[(long long)r1 * COUT + cb] = make_float2(v10, v11);
        float s0 = (v0 ? v00 : 0.0f) + (v1 ? v10 : 0.0f);
        float s1 = (v0 ? v01 : 0.0f) + (v1 ? v11 : 0.0f);
        float q0 = (v0 ? v00 * v00 : 0.0f) + (v1 ? v10 * v10 : 0.0f);
        float q1 = (v0 ? v01 * v01 : 0.0f) + (v1 ? v11 * v11 : 0.0f);
        cs[2 * j] = s0; cs[2 * j + 1] = s1;
        cq[2 * j] = q0; cq[2 * j + 1] = q1;
    }
    // reduce across gid (lane bits 2,3,4)
#pragma unroll
    for (int k = 4; k <= 16; k <<= 1) {
#pragma unroll
        for (int i = 0; i < 24; ++i) {
            cs[i] += __shfl_xor_sync(0xffffffffu, cs[i], k);
            cq[i] += __shfl_xor_sync(0xffffffffu, cq[i], k);
        }
    }
    if (gid == 0) {
#pragma unroll
        for (int j = 0; j < 12; ++j) {
            int col = wn * 96 + j * 8 + 2 * tig;
            RedS[wm * COUT + col]     = cs[2 * j];
            RedS[wm * COUT + col + 1] = cs[2 * j + 1];
            RedQ[wm * COUT + col]     = cq[2 * j];
            RedQ[wm * COUT + col + 1] = cq[2 * j + 1];
        }
    }
    __syncthreads();
    if (tid < COUT) {
        float s = 0.0f, q = 0.0f;
#pragma unroll
        for (int y = 0; y < 4; ++y) {
            s += RedS[y * COUT + tid];
            q += RedQ[y * COUT + tid];
        }
        g_psum[tid * NBLK + bx] = s;
        g_psq[tid * NBLK + bx]  = q;
    }
}

// ---------------------------------------------------------------------------
// Stats kernel: reduce partials -> fused scale/shift.
// ---------------------------------------------------------------------------
__global__ __launch_bounds__(256) void stats_kernel(
    const float* __restrict__ gamma,
    const float* __restrict__ beta)
{
    const int c = blockIdx.x;
    const int t = threadIdx.x;
    float s = 0.0f, q = 0.0f;
    for (int b = t; b < NBLK; b += 256) {
        s += g_psum[c * NBLK + b];
        q += g_psq[c * NBLK + b];
    }
    __shared__ float ss[256], sq[256];
    ss[t] = s; sq[t] = q;
    __syncthreads();
    for (int o = 128; o > 0; o >>= 1) {
        if (t < o) { ss[t] += ss[t + o]; sq[t] += sq[t + o]; }
        __syncthreads();
    }
    if (t == 0) {
        float mean = ss[0] / (float)M_OUT;
        float var  = sq[0] / (float)M_OUT - mean * mean;
        float rs   = rsqrtf(var + BN_EPS);
        float sc   = gamma[c] * rs;
        g_scale[c] = sc;
        g_shift[c] = beta[c] - mean * sc;
    }
}

// ---------------------------------------------------------------------------
// Normalize kernel: in-place float4 affine over d_out.
// ---------------------------------------------------------------------------
#define NVEC (M_OUT * COUT / 4)   // 6,000,000
__global__ __launch_bounds__(256) void norm_kernel(float4* __restrict__ out4)
{
    int i = blockIdx.x * 256 + threadIdx.x;
    if (i < NVEC) {
        int c = (i % 48) * 4;
        float4 v = out4[i];
        v.x = v.x * g_scale[c + 0] + g_shift[c + 0];
        v.y = v.y * g_scale[c + 1] + g_shift[c + 1];
        v.z = v.z * g_scale[c + 2] + g_shift[c + 2];
        v.w = v.w * g_scale[c + 3] + g_shift[c + 3];
        out4[i] = v;
    }
}

extern "C" void kernel_launch(void* const* d_in, const int* in_sizes, int n_in,
                              void* d_out, int out_size)
{
    const float* data    = (const float*)d_in[0];
    const float* weights = (const float*)d_in[1];
    const float* bias    = (const float*)d_in[2];
    const float* gamma   = (const float*)d_in[3];
    const float* beta    = (const float*)d_in[4];
    const void*  neigh   = (const void*)d_in[5];
    float* out = (float*)d_out;

    detect_kernel<<<1, 32>>>((const int*)neigh);
    prepack_kernel<<<NCHUNK, 256>>>(weights);
    conv_kernel<<<NBLK, 256>>>(data, bias, neigh, out);
    stats_kernel<<<COUT, 256>>>(gamma, beta);
    norm_kernel<<<(NVEC + 255) / 256, 256>>>((float4*)out);
}